// round 16
// baseline (speedup 1.0000x reference)
#include <cuda_runtime.h>
#include <cuda_bf16.h>
#include <cstdint>

#define XDIM 128
#define X3   (XDIM * XDIM * XDIM)   // 2,097,152 voxels
#define NB   16                     // batch
#define RBLK 512                    // reduce blocks (16 x 32)

// Grid in bf16, batch-minor: g_grid[v*NB + b]. 64 MiB, zero-init at load.
// INVARIANT: all-zero at entry to every kernel_launch. Per launch:
// scatter -> reduce (zeroes nonzero INTERIOR chunks: y%8!=0 && z%4!=0, which
// only their own block reads; records nonzero BOUNDARY chunks in g_bmask) ->
// boundary-zero via masks + finalize. Nonzero bits <=> touched: bf16
// accumulator starting at +0 under RN addition never yields -0.0 or a
// nonzero encoding of zero; and per-16B granule, bits==0 means already zero.
__device__ __nv_bfloat16 g_grid[(size_t)X3 * NB];
__device__ double   g_acc[2 * NB];        // [0..15] tv, [16..31] mse
__device__ unsigned g_bmask[RBLK * 256];  // per reduce-thread boundary mask

// ---------------------------------------------------------------------------
// Scatter (r5 proven): one thread per index; 2 x red.v4.bf16x2 (16 batches).
// ---------------------------------------------------------------------------
__global__ void scatter_kernel(const int* __restrict__ idx,
                               const float* __restrict__ vals, int N) {
    int n = blockIdx.x * blockDim.x + threadIdx.x;
    if (n >= N) return;
    int z = __ldcs(idx + 3 * n + 0);
    int y = __ldcs(idx + 3 * n + 1);
    int x = __ldcs(idx + 3 * n + 2);
    size_t v = (size_t)(((z << 7) + y) * XDIM + x);

    unsigned w[8];
#pragma unroll
    for (int g = 0; g < 8; g++) {
        float a = __ldcs(vals + (size_t)(2 * g) * N + n);
        float b = __ldcs(vals + (size_t)(2 * g + 1) * N + n);
        __nv_bfloat162 p = __floats2bfloat162_rn(a, b);
        w[g] = *reinterpret_cast<unsigned*>(&p);
    }

    __nv_bfloat16* base = g_grid + v * NB;
    asm volatile("red.global.add.noftz.v4.bf16x2 [%0], {%1, %2, %3, %4};"
                 :: "l"(base), "r"(w[0]), "r"(w[1]), "r"(w[2]), "r"(w[3])
                 : "memory");
    asm volatile("red.global.add.noftz.v4.bf16x2 [%0], {%1, %2, %3, %4};"
                 :: "l"(base + 8), "r"(w[4]), "r"(w[5]), "r"(w[6]), "r"(w[7])
                 : "memory");
}

// ---------------------------------------------------------------------------
// Packed diff-accumulate (proven r4): HADD2 diff, shl/and unpack, FADD |.|
// TV, packed fma.rn.f32x2 MSE.
// ---------------------------------------------------------------------------
#define ACCW(sw, nw, k, mp) do {                                              \
    __nv_bfloat162 _a = *reinterpret_cast<const __nv_bfloat162*>(&(nw));      \
    __nv_bfloat162 _b = *reinterpret_cast<const __nv_bfloat162*>(&(sw));      \
    __nv_bfloat162 _d = __hsub2(_a, _b);                                      \
    unsigned _du = *reinterpret_cast<unsigned*>(&_d);                         \
    float _lo = __uint_as_float(_du << 16);                                   \
    float _hi = __uint_as_float(_du & 0xffff0000u);                           \
    tv[(k)]     += fabsf(_lo);                                                \
    tv[(k) + 1] += fabsf(_hi);                                                \
    unsigned long long _dp;                                                   \
    asm("mov.b64 %0, {%1, %2};" : "=l"(_dp)                                   \
        : "r"(__float_as_uint(_lo)), "r"(__float_as_uint(_hi)));              \
    asm("fma.rn.f32x2 %0, %1, %2, %3;" : "=l"(mp)                             \
        : "l"(_dp), "l"(_dp), "l"(mp));                                       \
} while (0)

#define ACC4(s, nb) do {                                                      \
    ACCW((s).x, (nb).x, 0, msep[0]);                                          \
    ACCW((s).y, (nb).y, 2, msep[1]);                                          \
    ACCW((s).z, (nb).z, 4, msep[2]);                                          \
    ACCW((s).w, (nb).w, 6, msep[3]);                                          \
} while (0)

// ---------------------------------------------------------------------------
// Reduce (r5 proven tiling): grid = 16 y-octets x 32 z-quads, block = 8
// warps, warp = one y row, 4 z-plane loop. Tracks nonzero self chunks in a
// 32-bit mask (bit zi*8+c). Interior bits (wrp!=0 && zi!=0) are zeroed here
// after the block sync; boundary bits are handed to zero_fin via g_bmask.
// ---------------------------------------------------------------------------
__global__ void reduce_kernel() {
    const uint4* __restrict__ g4 = (const uint4*)g_grid;
    uint4* __restrict__ gw = (uint4*)g_grid;
    int tid  = threadIdx.x;
    int lane = tid & 31;
    int wrp  = tid >> 5;             // 0..7 ; y%8 == wrp
    int bg   = lane & 1;
    int xl   = lane >> 1;            // 0..15
    int y    = blockIdx.x * 8 + wrp; // 0..127
    bool yok = (y < XDIM - 1);

    float tv[8];
    unsigned long long msep[4];
#pragma unroll
    for (int i = 0; i < 8; i++) tv[i] = 0.f;
#pragma unroll
    for (int i = 0; i < 4; i++) msep[i] = 0ull;

    unsigned zmask = 0u;             // bit zi*8+c: self chunk nonzero

    for (int zi = 0; zi < 4; zi++) {
        int z = blockIdx.y * 4 + zi;
        bool zok = (z < XDIM - 1);
        size_t row2 = ((size_t)(z << 7) + y) * (XDIM * 2);  // uint4 idx at x=0

#pragma unroll
        for (int c = 0; c < 8; c++) {
            size_t i0 = row2 + c * 32 + lane;
            uint4 s = g4[i0];
            if ((s.x | s.y | s.z | s.w) != 0u)
                zmask |= (1u << (zi * 8 + c));

            if (c < 7) {
                uint4 nx = g4[i0 + 2];
                ACC4(s, nx);
            } else if (xl < 15) {                  // x = 112..126 only
                uint4 nx = g4[i0 + 2];
                ACC4(s, nx);
            }
            if (yok) { uint4 ny = g4[i0 + 2 * XDIM];        ACC4(s, ny); }
            if (zok) { uint4 nz = g4[i0 + 2 * XDIM * XDIM]; ACC4(s, nz); }
        }
    }

    // Split mask: interior chunks (this block is sole reader) vs boundary.
    unsigned intsel = (wrp != 0) ? 0xffffff00u : 0u;  // zi>=1 bits if y%8!=0
    unsigned imask  = zmask & intsel;
    int bid = blockIdx.y * 16 + blockIdx.x;
    g_bmask[bid * 256 + tid] = zmask & ~intsel;       // boundary handoff

    // Unpack packed mse pairs.
    float mse[8];
#pragma unroll
    for (int i = 0; i < 4; i++) {
        unsigned _lo, _hi;
        asm("mov.b64 {%0, %1}, %2;" : "=r"(_lo), "=r"(_hi) : "l"(msep[i]));
        mse[2 * i]     = __uint_as_float(_lo);
        mse[2 * i + 1] = __uint_as_float(_hi);
    }

    // Warp reduce over lanes sharing bg (stride-2 lanes): xor 2,4,8,16.
#pragma unroll
    for (int off = 2; off <= 16; off <<= 1) {
#pragma unroll
        for (int i = 0; i < 8; i++) {
            tv[i]  += __shfl_xor_sync(0xffffffffu, tv[i],  off);
            mse[i] += __shfl_xor_sync(0xffffffffu, mse[i], off);
        }
    }

    __shared__ float s_tv[NB], s_mse[NB];
    if (tid < NB) { s_tv[tid] = 0.f; s_mse[tid] = 0.f; }
    __syncthreads();   // ALL grid reads by this block complete beyond here

    // Zero this block's touched interior chunks (exclusive ownership).
    if (imask) {
        uint4 z4 = make_uint4(0u, 0u, 0u, 0u);
        for (int zi = 1; zi < 4; zi++) {
            if ((imask >> (zi * 8)) & 0xffu) {
                int z = blockIdx.y * 4 + zi;
                size_t row2 = ((size_t)(z << 7) + y) * (XDIM * 2);
#pragma unroll
                for (int c = 0; c < 8; c++) {
                    if (imask & (1u << (zi * 8 + c)))
                        gw[row2 + c * 32 + lane] = z4;
                }
            }
        }
    }

    if (lane < 2) {                  // lane 0 = bg0 totals, lane 1 = bg1
#pragma unroll
        for (int i = 0; i < 8; i++) {
            atomicAdd(&s_tv[bg * 8 + i],  tv[i]);
            atomicAdd(&s_mse[bg * 8 + i], mse[i]);
        }
    }
    __syncthreads();

    if (tid < NB) {
        atomicAdd(&g_acc[tid],      (double)s_tv[tid]);
        atomicAdd(&g_acc[NB + tid], (double)s_mse[tid]);
    }
}

// ---------------------------------------------------------------------------
// Boundary zero via masks: same thread geometry as reduce; each thread reads
// its 32-bit boundary mask (512 KB total) and stores one 16B zero per set
// bit. No index reads, no wasted threads. Block RBLK finalizes.
// ---------------------------------------------------------------------------
__global__ void zero_fin_kernel(float* __restrict__ out) {
    if (blockIdx.x == RBLK) {
        int t = threadIdx.x;
        if (t < 32) {
            double norm = (t < NB) ? (double)X3
                                   : (double)(2 * XDIM * XDIM - 2 * XDIM);
            out[t] = (float)(g_acc[t] / norm);
            g_acc[t] = 0.0;          // restore invariant for next replay
        }
        return;
    }
    int tid  = threadIdx.x;
    int lane = tid & 31;
    int wrp  = tid >> 5;
    int b    = blockIdx.x;           // == reduce bid
    int bx   = b & 15;
    int by   = b >> 4;
    int y    = bx * 8 + wrp;

    unsigned m = g_bmask[b * 256 + tid];
    if (!m) return;

    uint4* __restrict__ gw = (uint4*)g_grid;
    uint4 z4 = make_uint4(0u, 0u, 0u, 0u);
    do {
        int bit = __ffs(m) - 1;
        m &= m - 1;
        int zi = bit >> 3;
        int c  = bit & 7;
        int z  = by * 4 + zi;
        size_t row2 = ((size_t)(z << 7) + y) * (XDIM * 2);
        gw[row2 + c * 32 + lane] = z4;
    } while (m);
}

extern "C" void kernel_launch(void* const* d_in, const int* in_sizes, int n_in,
                              void* d_out, int out_size) {
    const int*   indices = (const int*)d_in[0];
    const float* values  = (const float*)d_in[1];
    int N = in_sizes[0] / 3;        // 500000

    scatter_kernel<<<(N + 255) / 256, 256>>>(indices, values, N);
    reduce_kernel<<<dim3(16, 32), 256>>>();
    zero_fin_kernel<<<RBLK + 1, 256>>>((float*)d_out);
}